// round 14
// baseline (speedup 1.0000x reference)
#include <cuda_runtime.h>
#include <cuda_bf16.h>
#include <math.h>
#include <stdint.h>

// Problem constants
#define BB 4
#define NN 16384
#define NVV 16384
#define DD 256
#define NHH 8
#define PP 4

// Scratch (device globals — no runtime allocation allowed)
__device__ float g_v[(size_t)BB * NVV * DD];        // 64 MB
__device__ float g_weighted[(size_t)BB * NN * DD];  // 64 MB
__device__ float g_proj[(size_t)BB * NN * 128];     // 32 MB: off(64)|attn(32)|pad
__device__ __nv_bfloat16 g_wv_hi[DD * DD], g_wv_lo[DD * DD];
__device__ __nv_bfloat16 g_wo_hi[DD * DD], g_wo_lo[DD * DD];
__device__ __nv_bfloat16 g_wp_hi[128 * DD], g_wp_lo[128 * DD];
__device__ float g_bias_p[128];
__device__ int g_list[(size_t)BB * NN * 64];        // flagged coord ids
__device__ int g_count[1];

__device__ __forceinline__ uint32_t smem_u32(const void* p) {
    uint32_t a;
    asm("{ .reg .u64 t; cvta.to.shared.u64 t, %1; cvt.u32.u64 %0, t; }"
        : "=r"(a) : "l"(p));
    return a;
}

#define LDSM_X4(r0, r1, r2, r3, addr)                                          \
    asm volatile("ldmatrix.sync.aligned.m8n8.x4.shared.b16 {%0,%1,%2,%3}, [%4];" \
                 : "=r"(r0), "=r"(r1), "=r"(r2), "=r"(r3) : "r"(addr))
#define LDSM_X2(r0, r1, addr)                                                  \
    asm volatile("ldmatrix.sync.aligned.m8n8.x2.shared.b16 {%0,%1}, [%2];"     \
                 : "=r"(r0), "=r"(r1) : "r"(addr))
#define MMA16816(acc, a, b)                                                    \
    asm volatile(                                                              \
        "mma.sync.aligned.m16n8k16.row.col.f32.bf16.bf16.f32 "                 \
        "{%0,%1,%2,%3}, {%4,%5,%6,%7}, {%8,%9}, {%0,%1,%2,%3};"                \
        : "+f"((acc)[0]), "+f"((acc)[1]), "+f"((acc)[2]), "+f"((acc)[3])       \
        : "r"((a)[0]), "r"((a)[1]), "r"((a)[2]), "r"((a)[3]),                  \
          "r"((b)[0]), "r"((b)[1]))
#define CP_ASYNC16(dst, src)                                                   \
    asm volatile("cp.async.cg.shared.global [%0], [%1], 16;"                   \
                 :: "r"(dst), "l"(src))
#define CP_COMMIT() asm volatile("cp.async.commit_group;" ::: "memory")
#define CP_WAIT0()  asm volatile("cp.async.wait_group 0;" ::: "memory")

#define DELTA 6e-3f
#define STAGE_CAP 2048

// ===========================================================================
// Weight prep (unchanged — validated)
// ===========================================================================
__global__ void prep_weight(const float* __restrict__ W,
                            __nv_bfloat16* __restrict__ hi,
                            __nv_bfloat16* __restrict__ lo, int Nw) {
    int id = blockIdx.x * 256 + threadIdx.x;  // id = n*256 + k
    int n = id >> 8, k = id & 255;
    float v = W[(size_t)k * Nw + n];
    __nv_bfloat16 h = __float2bfloat16_rn(v);
    hi[id] = h;
    lo[id] = __float2bfloat16_rn(v - __bfloat162float(h));
}

__global__ void prep_weight_proj(const float* __restrict__ Woff,
                                 const float* __restrict__ Wattn,
                                 const float* __restrict__ boff,
                                 const float* __restrict__ battn,
                                 __nv_bfloat16* __restrict__ hi,
                                 __nv_bfloat16* __restrict__ lo,
                                 float* __restrict__ biasp,
                                 int* __restrict__ counter) {
    int id = blockIdx.x * 256 + threadIdx.x;  // 128*256 total
    int n = id >> 8, k = id & 255;
    float v = 0.0f;
    if (n < 64) v = Woff[(size_t)k * 64 + n];
    else if (n < 96) v = Wattn[(size_t)k * 32 + (n - 64)];
    __nv_bfloat16 h = __float2bfloat16_rn(v);
    hi[id] = h;
    lo[id] = __float2bfloat16_rn(v - __bfloat162float(h));
    if (id < 128)
        biasp[id] = (id < 64) ? boff[id] : (id < 96 ? battn[id - 64] : 0.0f);
    if (id == 0) counter[0] = 0;
}

// ===========================================================================
// Tensor-core GEMM (bf16x3 split), double-buffered K=32 pipeline.
// CTA tile 128 x (NJ*32); warp tile 64 x (NJ*8); 2 CTAs/SM (validated R11).
// DO_FLAG: proj variant — fused δ-band flagging in the epilogue (predicate
// math identical to the validated flag_kernel, applied to the identical
// stored fp32 value; flagged-id SET identical; fixup is order-independent).
// Per-accumulator k16 order 0..15 ascending, same 3-term split order =>
// bitwise identical accumulation to the validated kernel.
// ===========================================================================
#define S40 40
#define TILE40 (128 * S40)
#define BUF40 (4 * TILE40)
#define OFF_AHI 0
#define OFF_ALO TILE40
#define OFF_BHI (2 * TILE40)
#define OFF_BLO (3 * TILE40)

template <int CN, int NJ, bool DO_FLAG>
__global__ void __launch_bounds__(256, 2) gemm_mma(
    const float* __restrict__ A,
    const __nv_bfloat16* __restrict__ Bhi,
    const __nv_bfloat16* __restrict__ Blo,
    const float* __restrict__ bias,
    float* __restrict__ C,
    const float* __restrict__ refp,
    int* __restrict__ list,
    int* __restrict__ counter) {
    extern __shared__ __nv_bfloat16 sm[];
    float* s_bias = reinterpret_cast<float*>(sm + 2 * BUF40);
    __shared__ int s_cnt, s_base;
    __shared__ int s_stage[DO_FLAG ? STAGE_CAP : 1];

    constexpr int NT = NJ * 32;  // CTA N-tile (96 or 128)
    const int tid = threadIdx.x;
    const int wid = tid >> 5;
    const int lane = tid & 31;
    const int rowBase = blockIdx.y * 128;
    const int colBase = blockIdx.x * 128;
    const int warpRow = (wid >> 2) * 64;
    const int warpCol = (wid & 3) * (NJ * 8);
    const uint32_t sb = smem_u32(sm);

    if (tid < NT) s_bias[tid] = bias[colBase + tid];

    float acc[4][NJ][4];
#pragma unroll
    for (int i = 0; i < 4; i++)
#pragma unroll
        for (int j = 0; j < NJ; j++)
#pragma unroll
            for (int r = 0; r < 4; r++) acc[i][j][r] = 0.0f;

    const int a_r = tid >> 3, a_c = (tid & 7) * 4;
    const int b_n = tid >> 2, b_c = (tid & 3) * 8;

    const int fa_row = warpRow + (lane & 7) + (lane & 8);
    const int fa_col = (lane >> 4) * 8;
    const uint32_t fa_off = (uint32_t)(fa_row * S40 + fa_col) * 2;
    const int fb_row = warpCol + (lane & 7);
    const int fb_col = ((lane >> 3) & 1) * 8;
    const uint32_t fb_off = (uint32_t)(fb_row * S40 + fb_col) * 2;

    float4 pa[4];

    auto loadB_async = [&](int k0, int buf) {
        uint32_t base = sb + (uint32_t)(buf * BUF40) * 2;
#pragma unroll
        for (int it = 0; it < 2; it++) {
            int n = b_n + it * 64;
            if (n < NT) {
                uint32_t d = (uint32_t)(n * S40 + b_c) * 2;
                CP_ASYNC16(base + (OFF_BHI * 2) + d,
                           &Bhi[(size_t)(colBase + n) * 256 + k0 + b_c]);
                CP_ASYNC16(base + (OFF_BLO * 2) + d,
                           &Blo[(size_t)(colBase + n) * 256 + k0 + b_c]);
            }
        }
    };
    auto loadA_regs = [&](int k0) {
#pragma unroll
        for (int it = 0; it < 4; it++) {
            int row = a_r + it * 32;
            pa[it] = *reinterpret_cast<const float4*>(
                &A[(size_t)(rowBase + row) * 256 + k0 + a_c]);
        }
    };
    auto convA_sts = [&](int buf) {
        __nv_bfloat16* Ah = sm + buf * BUF40 + OFF_AHI;
        __nv_bfloat16* Al = sm + buf * BUF40 + OFF_ALO;
#pragma unroll
        for (int it = 0; it < 4; it++) {
            int row = a_r + it * 32;
            float f[4] = {pa[it].x, pa[it].y, pa[it].z, pa[it].w};
            uint32_t hw[2], lw[2];
#pragma unroll
            for (int j = 0; j < 2; j++) {
                __nv_bfloat16 h0 = __float2bfloat16_rn(f[2 * j]);
                __nv_bfloat16 h1 = __float2bfloat16_rn(f[2 * j + 1]);
                __nv_bfloat16 l0 = __float2bfloat16_rn(f[2 * j] - __bfloat162float(h0));
                __nv_bfloat16 l1 = __float2bfloat16_rn(f[2 * j + 1] - __bfloat162float(h1));
                hw[j] = (uint32_t)__bfloat16_as_ushort(h0) |
                        ((uint32_t)__bfloat16_as_ushort(h1) << 16);
                lw[j] = (uint32_t)__bfloat16_as_ushort(l0) |
                        ((uint32_t)__bfloat16_as_ushort(l1) << 16);
            }
            *reinterpret_cast<uint2*>(&Ah[row * S40 + a_c]) = make_uint2(hw[0], hw[1]);
            *reinterpret_cast<uint2*>(&Al[row * S40 + a_c]) = make_uint2(lw[0], lw[1]);
        }
    };

    loadB_async(0, 0);
    CP_COMMIT();
    loadA_regs(0);
    convA_sts(0);
    CP_WAIT0();
    __syncthreads();

    for (int c = 0; c < 8; c++) {
        const int cur = c & 1;
        const bool more = (c < 7);
        if (more) {
            loadB_async((c + 1) * 32, cur ^ 1);
            CP_COMMIT();
            loadA_regs((c + 1) * 32);
        }

        const uint32_t bufB = sb + (uint32_t)(cur * BUF40) * 2;
        const uint32_t aH = bufB + OFF_AHI * 2 + fa_off;
        const uint32_t aL = bufB + OFF_ALO * 2 + fa_off;
        const uint32_t bH = bufB + OFF_BHI * 2 + fb_off;
        const uint32_t bL = bufB + OFF_BLO * 2 + fb_off;
#pragma unroll
        for (int ks = 0; ks < 2; ks++) {
            const uint32_t kof = ks * 32;
            uint32_t bh[NJ][2], bl[NJ][2];
#pragma unroll
            for (int j = 0; j < NJ; j++) {
                LDSM_X2(bh[j][0], bh[j][1], bH + j * (8 * S40 * 2) + kof);
                LDSM_X2(bl[j][0], bl[j][1], bL + j * (8 * S40 * 2) + kof);
            }
#pragma unroll
            for (int i = 0; i < 4; i++) {
                uint32_t ah[4], al[4];
                LDSM_X4(ah[0], ah[1], ah[2], ah[3], aH + i * (16 * S40 * 2) + kof);
                LDSM_X4(al[0], al[1], al[2], al[3], aL + i * (16 * S40 * 2) + kof);
#pragma unroll
                for (int j = 0; j < NJ; j++) {
                    MMA16816(acc[i][j], ah, bh[j]);
                    MMA16816(acc[i][j], ah, bl[j]);
                    MMA16816(acc[i][j], al, bh[j]);
                }
            }
        }

        if (more) {
            convA_sts(cur ^ 1);
            CP_WAIT0();
        }
        __syncthreads();
    }

    if (DO_FLAG) {
        if (tid == 0) s_cnt = 0;
        __syncthreads();
    }

    // ---- epilogue (+ fused δ-band flagging for the proj variant) ----
    const int g = lane >> 2, c2 = (lane & 3) * 2;
#pragma unroll
    for (int i = 0; i < 4; i++) {
        int r0 = rowBase + warpRow + i * 16 + g;
        float2 rp0, rp8;
        if (DO_FLAG && warpCol < 64) {
            rp0 = *reinterpret_cast<const float2*>(&refp[(size_t)r0 * 2]);
            rp8 = *reinterpret_cast<const float2*>(&refp[(size_t)(r0 + 8) * 2]);
        }
#pragma unroll
        for (int j = 0; j < NJ; j++) {
            int col = warpCol + j * 8 + c2;
            float b0 = s_bias[col], b1 = s_bias[col + 1];
            float2 o0 = make_float2(acc[i][j][0] + b0, acc[i][j][1] + b1);
            float2 o1 = make_float2(acc[i][j][2] + b0, acc[i][j][3] + b1);
            *reinterpret_cast<float2*>(&C[(size_t)r0 * CN + colBase + col]) = o0;
            *reinterpret_cast<float2*>(&C[(size_t)(r0 + 8) * CN + colBase + col]) = o1;

            if (DO_FLAG && col < 64) {
                // predicate EXACTLY as the validated flag_kernel, on the
                // identical stored fp32 values
                float ov[4] = {o0.x, o0.y, o1.x, o1.y};
                float rv[4] = {rp0.x, rp0.y, rp8.x, rp8.y};  // col even
                int qv[4] = {r0, r0, r0 + 8, r0 + 8};
                int cv[4] = {col, col + 1, col, col + 1};
#pragma unroll
                for (int t = 0; t < 4; t++) {
                    float lx = (rv[t] + ov[t]) * 2.0f - 1.0f;
                    float f = (lx + 1.0f) * 64.0f - 0.5f;
                    if (fabsf(f - floorf(f) - 0.5f) < DELTA) {
                        int id = qv[t] * 64 + cv[t];
                        int loc = atomicAdd(&s_cnt, 1);
                        if (loc < STAGE_CAP) s_stage[loc] = id;
                        else { int gg = atomicAdd(counter, 1); list[gg] = id; }
                    }
                }
            }
        }
    }

    if (DO_FLAG) {
        __syncthreads();
        if (tid == 0) {
            int n = min(s_cnt, STAGE_CAP);
            s_base = (n > 0) ? atomicAdd(counter, n) : 0;
        }
        __syncthreads();
        int n = min(s_cnt, STAGE_CAP);
        for (int k = tid; k < n; k += 256) list[s_base + k] = s_stage[k];
    }
}

// ---------------------------------------------------------------------------
// Fixup kernel (unchanged — validated; order-independent over disjoint ids)
// ---------------------------------------------------------------------------
__global__ void fixup_kernel(const int* __restrict__ list,
                             const int* __restrict__ counter,
                             const float* __restrict__ query,
                             const float* __restrict__ Woff,
                             const float* __restrict__ boff,
                             float* __restrict__ proj) {
    int total = counter[0];
    for (int i = blockIdx.x * blockDim.x + threadIdx.x; i < total;
         i += gridDim.x * blockDim.x) {
        int id = list[i];
        int q = id >> 6, col = id & 63;
        const float* qrow = query + (size_t)q * 256;
        const float* wcol = Woff + col;
        float acc = 0.0f;
#pragma unroll
        for (int k0 = 0; k0 < 256; k0 += 8) {
            float qv[8], wv[8];
#pragma unroll
            for (int j = 0; j < 8; j++) qv[j] = qrow[k0 + j];
#pragma unroll
            for (int j = 0; j < 8; j++) wv[j] = wcol[(size_t)(k0 + j) * 64];
#pragma unroll
            for (int j = 0; j < 8; j++) acc += qv[j] * wv[j];
        }
        proj[(size_t)q * 128 + col] = acc + boff[col];
    }
}

// ---------------------------------------------------------------------------
// Sampling kernel (unchanged — validated)
// ---------------------------------------------------------------------------
__global__ void sample_kernel(const float* __restrict__ refp,
                              const float* __restrict__ proj,
                              const float* __restrict__ v,
                              float* __restrict__ outw) {
    const int warpsPerBlock = blockDim.x >> 5;
    const int q = blockIdx.x * warpsPerBlock + (threadIdx.x >> 5);
    const int lane = threadIdx.x & 31;
    if (q >= BB * NN) return;
    const int b = q >> 14;

    const float* prow = proj + (size_t)q * 128;
    float logit = prow[64 + lane];
    float m = logit;
    m = fmaxf(m, __shfl_xor_sync(0xffffffffu, m, 1));
    m = fmaxf(m, __shfl_xor_sync(0xffffffffu, m, 2));
    float e = expf(logit - m);
    float s = e;
    s += __shfl_xor_sync(0xffffffffu, s, 1);
    s += __shfl_xor_sync(0xffffffffu, s, 2);
    float w = e / s;

    float rx = refp[(size_t)q * 2 + 0];
    float ry = refp[(size_t)q * 2 + 1];
    float ox = prow[lane * 2 + 0];
    float oy = prow[lane * 2 + 1];
    float lx = (rx + ox) * 2.0f - 1.0f;
    float ly = (ry + oy) * 2.0f - 1.0f;
    float fx = (lx + 1.0f) * 64.0f - 0.5f;
    float fy = (ly + 1.0f) * 64.0f - 0.5f;
    float ixf = rintf(fx);
    float iyf = rintf(fy);
    bool valid = (ixf >= 0.0f) && (ixf < 128.0f) && (iyf >= 0.0f) && (iyf < 128.0f);
    int flat = valid ? ((int)iyf * 128 + (int)ixf) : 0;
    float wv = valid ? w : 0.0f;

    const float* vb = v + (size_t)b * NVV * DD;
    const size_t outBase = (size_t)q * DD;
#pragma unroll
    for (int h = 0; h < NHH; h++) {
        float acc = 0.0f;
#pragma unroll
        for (int p = 0; p < PP; p++) {
            int src = h * 4 + p;
            float ww = __shfl_sync(0xffffffffu, wv, src);
            int fl = __shfl_sync(0xffffffffu, flat, src);
            if (ww != 0.0f) {
                acc += ww * vb[(size_t)fl * DD + h * 32 + lane];
            }
        }
        outw[outBase + h * 32 + lane] = acc;
    }
}

// ---------------------------------------------------------------------------
extern "C" void kernel_launch(void* const* d_in, const int* in_sizes, int n_in,
                              void* d_out, int out_size) {
    const float* query  = (const float*)d_in[0];
    const float* refp   = (const float*)d_in[1];
    const float* value  = (const float*)d_in[2];
    const float* W_off  = (const float*)d_in[3];
    const float* b_off  = (const float*)d_in[4];
    const float* W_attn = (const float*)d_in[5];
    const float* b_attn = (const float*)d_in[6];
    const float* W_v    = (const float*)d_in[7];
    const float* b_v    = (const float*)d_in[8];
    const float* W_out  = (const float*)d_in[9];
    const float* b_out  = (const float*)d_in[10];
    float* out = (float*)d_out;

    float *gv = nullptr, *gw = nullptr, *gp = nullptr, *gbp = nullptr;
    __nv_bfloat16 *wvh = nullptr, *wvl = nullptr, *woh = nullptr, *wol = nullptr;
    __nv_bfloat16 *wph = nullptr, *wpl = nullptr;
    int *glist = nullptr, *gcnt = nullptr;
    cudaGetSymbolAddress((void**)&gv, g_v);
    cudaGetSymbolAddress((void**)&gw, g_weighted);
    cudaGetSymbolAddress((void**)&gp, g_proj);
    cudaGetSymbolAddress((void**)&gbp, g_bias_p);
    cudaGetSymbolAddress((void**)&wvh, g_wv_hi);
    cudaGetSymbolAddress((void**)&wvl, g_wv_lo);
    cudaGetSymbolAddress((void**)&woh, g_wo_hi);
    cudaGetSymbolAddress((void**)&wol, g_wo_lo);
    cudaGetSymbolAddress((void**)&wph, g_wp_hi);
    cudaGetSymbolAddress((void**)&wpl, g_wp_lo);
    cudaGetSymbolAddress((void**)&glist, g_list);
    cudaGetSymbolAddress((void**)&gcnt, g_count);

    const int M = BB * NN;  // 65536
    const int SMEM = 2 * BUF40 * 2 + 128 * 4;  // 82432
    cudaFuncSetAttribute((const void*)gemm_mma<256, 4, false>,
                         cudaFuncAttributeMaxDynamicSharedMemorySize, SMEM);
    cudaFuncSetAttribute((const void*)gemm_mma<128, 3, true>,
                         cudaFuncAttributeMaxDynamicSharedMemorySize, SMEM);

    // 0. prep bf16-split transposed weights (+ counter reset)
    prep_weight<<<256, 256>>>(W_v, wvh, wvl, 256);
    prep_weight<<<256, 256>>>(W_out, woh, wol, 256);
    prep_weight_proj<<<128, 256>>>(W_off, W_attn, b_off, b_attn, wph, wpl,
                                   gbp, gcnt);

    // 1. v = value @ W_v + b_v (128x128 tiles, bf16x3, pipelined — R11)
    gemm_mma<256, 4, false><<<dim3(2, M / 128), 256, SMEM>>>(
        value, wvh, wvl, b_v, gv, nullptr, nullptr, nullptr);

    // 2. proj = query @ [W_off|W_attn] (NJ=3) with FUSED δ-band flagging
    gemm_mma<128, 3, true><<<dim3(1, M / 128), 256, SMEM>>>(
        query, wph, wpl, gbp, gp, refp, glist, gcnt);

    // 3. exact fixup of flagged coords
    fixup_kernel<<<512, 256>>>(glist, gcnt, query, W_off, b_off, gp);

    // 4. softmax + nearest gather + weighted sum
    sample_kernel<<<M / 8, 256>>>(refp, gp, gv, gw);

    // 5. out = weighted @ W_out + b_out (128x128 tiles, bf16x3, pipelined)
    gemm_mma<256, 4, false><<<dim3(2, M / 128), 256, SMEM>>>(
        gw, woh, wol, b_out, out, nullptr, nullptr, nullptr);
}

// round 15
// speedup vs baseline: 1.0368x; 1.0368x over previous
#include <cuda_runtime.h>
#include <cuda_bf16.h>
#include <math.h>
#include <stdint.h>

// Problem constants
#define BB 4
#define NN 16384
#define NVV 16384
#define DD 256
#define NHH 8
#define PP 4

// Scratch (device globals — no runtime allocation allowed)
__device__ float g_v[(size_t)BB * NVV * DD];        // 64 MB
__device__ float g_weighted[(size_t)BB * NN * DD];  // 64 MB
__device__ float g_proj[(size_t)BB * NN * 96];      // 24 MB: off(64)|attn(32)
__device__ __nv_bfloat16 g_wv_hi[DD * DD], g_wv_lo[DD * DD];
__device__ __nv_bfloat16 g_wo_hi[DD * DD], g_wo_lo[DD * DD];
__device__ __nv_bfloat16 g_wp_hi[128 * DD], g_wp_lo[128 * DD];
__device__ float g_bias_p[128];
__device__ int g_list[(size_t)BB * NN * 64];        // flagged coord ids
__device__ int g_count[1];

__device__ __forceinline__ uint32_t smem_u32(const void* p) {
    uint32_t a;
    asm("{ .reg .u64 t; cvta.to.shared.u64 t, %1; cvt.u32.u64 %0, t; }"
        : "=r"(a) : "l"(p));
    return a;
}

#define LDSM_X4(r0, r1, r2, r3, addr)                                          \
    asm volatile("ldmatrix.sync.aligned.m8n8.x4.shared.b16 {%0,%1,%2,%3}, [%4];" \
                 : "=r"(r0), "=r"(r1), "=r"(r2), "=r"(r3) : "r"(addr))
#define LDSM_X2(r0, r1, addr)                                                  \
    asm volatile("ldmatrix.sync.aligned.m8n8.x2.shared.b16 {%0,%1}, [%2];"     \
                 : "=r"(r0), "=r"(r1) : "r"(addr))
#define MMA16816(acc, a, b)                                                    \
    asm volatile(                                                              \
        "mma.sync.aligned.m16n8k16.row.col.f32.bf16.bf16.f32 "                 \
        "{%0,%1,%2,%3}, {%4,%5,%6,%7}, {%8,%9}, {%0,%1,%2,%3};"                \
        : "+f"((acc)[0]), "+f"((acc)[1]), "+f"((acc)[2]), "+f"((acc)[3])       \
        : "r"((a)[0]), "r"((a)[1]), "r"((a)[2]), "r"((a)[3]),                  \
          "r"((b)[0]), "r"((b)[1]))
#define CP_ASYNC16(dst, src)                                                   \
    asm volatile("cp.async.cg.shared.global [%0], [%1], 16;"                   \
                 :: "r"(dst), "l"(src))
#define CP_COMMIT() asm volatile("cp.async.commit_group;" ::: "memory")
#define CP_WAIT0()  asm volatile("cp.async.wait_group 0;" ::: "memory")

// ===========================================================================
// Weight prep (unchanged — validated)
// ===========================================================================
__global__ void prep_weight(const float* __restrict__ W,
                            __nv_bfloat16* __restrict__ hi,
                            __nv_bfloat16* __restrict__ lo, int Nw) {
    int id = blockIdx.x * 256 + threadIdx.x;  // id = n*256 + k
    int n = id >> 8, k = id & 255;
    float v = W[(size_t)k * Nw + n];
    __nv_bfloat16 h = __float2bfloat16_rn(v);
    hi[id] = h;
    lo[id] = __float2bfloat16_rn(v - __bfloat162float(h));
}

__global__ void prep_weight_proj(const float* __restrict__ Woff,
                                 const float* __restrict__ Wattn,
                                 const float* __restrict__ boff,
                                 const float* __restrict__ battn,
                                 __nv_bfloat16* __restrict__ hi,
                                 __nv_bfloat16* __restrict__ lo,
                                 float* __restrict__ biasp,
                                 int* __restrict__ counter) {
    int id = blockIdx.x * 256 + threadIdx.x;  // 128*256 total
    int n = id >> 8, k = id & 255;
    float v = 0.0f;
    if (n < 64) v = Woff[(size_t)k * 64 + n];
    else if (n < 96) v = Wattn[(size_t)k * 32 + (n - 64)];
    __nv_bfloat16 h = __float2bfloat16_rn(v);
    hi[id] = h;
    lo[id] = __float2bfloat16_rn(v - __bfloat162float(h));
    if (id < 128)
        biasp[id] = (id < 64) ? boff[id] : (id < 96 ? battn[id - 64] : 0.0f);
    if (id == 0) counter[0] = 0;
}

// ===========================================================================
// Tensor-core GEMM (bf16x3 split), double-buffered K=32 pipeline.
// CTA tile 128 x (NJ*32); warp tile 64 x (NJ*8); 2 CTAs/SM (validated R11).
// NJ=4 for the 128-col tiles of the 256-wide GEMMs; NJ=3/CN=96 for the proj.
// Per-accumulator k16 order 0..15 ascending, same 3-term split order =>
// bitwise identical accumulation to the validated kernel.
// ===========================================================================
#define S40 40
#define TILE40 (128 * S40)
#define BUF40 (4 * TILE40)
#define OFF_AHI 0
#define OFF_ALO TILE40
#define OFF_BHI (2 * TILE40)
#define OFF_BLO (3 * TILE40)

template <int CN, int NJ>
__global__ void __launch_bounds__(256, 2) gemm_mma(
    const float* __restrict__ A,
    const __nv_bfloat16* __restrict__ Bhi,
    const __nv_bfloat16* __restrict__ Blo,
    const float* __restrict__ bias,
    float* __restrict__ C) {
    extern __shared__ __nv_bfloat16 sm[];
    float* s_bias = reinterpret_cast<float*>(sm + 2 * BUF40);

    constexpr int NT = NJ * 32;  // CTA N-tile (96 or 128)
    const int tid = threadIdx.x;
    const int wid = tid >> 5;
    const int lane = tid & 31;
    const int rowBase = blockIdx.y * 128;
    const int colBase = blockIdx.x * 128;
    const int warpRow = (wid >> 2) * 64;
    const int warpCol = (wid & 3) * (NJ * 8);
    const uint32_t sb = smem_u32(sm);

    if (tid < NT) s_bias[tid] = bias[colBase + tid];

    float acc[4][NJ][4];
#pragma unroll
    for (int i = 0; i < 4; i++)
#pragma unroll
        for (int j = 0; j < NJ; j++)
#pragma unroll
            for (int r = 0; r < 4; r++) acc[i][j][r] = 0.0f;

    const int a_r = tid >> 3, a_c = (tid & 7) * 4;
    const int b_n = tid >> 2, b_c = (tid & 3) * 8;

    const int fa_row = warpRow + (lane & 7) + (lane & 8);
    const int fa_col = (lane >> 4) * 8;
    const uint32_t fa_off = (uint32_t)(fa_row * S40 + fa_col) * 2;
    const int fb_row = warpCol + (lane & 7);
    const int fb_col = ((lane >> 3) & 1) * 8;
    const uint32_t fb_off = (uint32_t)(fb_row * S40 + fb_col) * 2;

    float4 pa[4];

    auto loadB_async = [&](int k0, int buf) {
        uint32_t base = sb + (uint32_t)(buf * BUF40) * 2;
#pragma unroll
        for (int it = 0; it < 2; it++) {
            int n = b_n + it * 64;
            if (n < NT) {
                uint32_t d = (uint32_t)(n * S40 + b_c) * 2;
                CP_ASYNC16(base + (OFF_BHI * 2) + d,
                           &Bhi[(size_t)(colBase + n) * 256 + k0 + b_c]);
                CP_ASYNC16(base + (OFF_BLO * 2) + d,
                           &Blo[(size_t)(colBase + n) * 256 + k0 + b_c]);
            }
        }
    };
    auto loadA_regs = [&](int k0) {
#pragma unroll
        for (int it = 0; it < 4; it++) {
            int row = a_r + it * 32;
            pa[it] = *reinterpret_cast<const float4*>(
                &A[(size_t)(rowBase + row) * 256 + k0 + a_c]);
        }
    };
    auto convA_sts = [&](int buf) {
        __nv_bfloat16* Ah = sm + buf * BUF40 + OFF_AHI;
        __nv_bfloat16* Al = sm + buf * BUF40 + OFF_ALO;
#pragma unroll
        for (int it = 0; it < 4; it++) {
            int row = a_r + it * 32;
            float f[4] = {pa[it].x, pa[it].y, pa[it].z, pa[it].w};
            uint32_t hw[2], lw[2];
#pragma unroll
            for (int j = 0; j < 2; j++) {
                __nv_bfloat16 h0 = __float2bfloat16_rn(f[2 * j]);
                __nv_bfloat16 h1 = __float2bfloat16_rn(f[2 * j + 1]);
                __nv_bfloat16 l0 = __float2bfloat16_rn(f[2 * j] - __bfloat162float(h0));
                __nv_bfloat16 l1 = __float2bfloat16_rn(f[2 * j + 1] - __bfloat162float(h1));
                hw[j] = (uint32_t)__bfloat16_as_ushort(h0) |
                        ((uint32_t)__bfloat16_as_ushort(h1) << 16);
                lw[j] = (uint32_t)__bfloat16_as_ushort(l0) |
                        ((uint32_t)__bfloat16_as_ushort(l1) << 16);
            }
            *reinterpret_cast<uint2*>(&Ah[row * S40 + a_c]) = make_uint2(hw[0], hw[1]);
            *reinterpret_cast<uint2*>(&Al[row * S40 + a_c]) = make_uint2(lw[0], lw[1]);
        }
    };

    loadB_async(0, 0);
    CP_COMMIT();
    loadA_regs(0);
    convA_sts(0);
    CP_WAIT0();
    __syncthreads();

    for (int c = 0; c < 8; c++) {
        const int cur = c & 1;
        const bool more = (c < 7);
        if (more) {
            loadB_async((c + 1) * 32, cur ^ 1);
            CP_COMMIT();
            loadA_regs((c + 1) * 32);
        }

        const uint32_t bufB = sb + (uint32_t)(cur * BUF40) * 2;
        const uint32_t aH = bufB + OFF_AHI * 2 + fa_off;
        const uint32_t aL = bufB + OFF_ALO * 2 + fa_off;
        const uint32_t bH = bufB + OFF_BHI * 2 + fb_off;
        const uint32_t bL = bufB + OFF_BLO * 2 + fb_off;
#pragma unroll
        for (int ks = 0; ks < 2; ks++) {
            const uint32_t kof = ks * 32;
            uint32_t bh[NJ][2], bl[NJ][2];
#pragma unroll
            for (int j = 0; j < NJ; j++) {
                LDSM_X2(bh[j][0], bh[j][1], bH + j * (8 * S40 * 2) + kof);
                LDSM_X2(bl[j][0], bl[j][1], bL + j * (8 * S40 * 2) + kof);
            }
#pragma unroll
            for (int i = 0; i < 4; i++) {
                uint32_t ah[4], al[4];
                LDSM_X4(ah[0], ah[1], ah[2], ah[3], aH + i * (16 * S40 * 2) + kof);
                LDSM_X4(al[0], al[1], al[2], al[3], aL + i * (16 * S40 * 2) + kof);
#pragma unroll
                for (int j = 0; j < NJ; j++) {
                    MMA16816(acc[i][j], ah, bh[j]);
                    MMA16816(acc[i][j], ah, bl[j]);
                    MMA16816(acc[i][j], al, bh[j]);
                }
            }
        }

        if (more) {
            convA_sts(cur ^ 1);
            CP_WAIT0();
        }
        __syncthreads();
    }

    const int g = lane >> 2, c2 = (lane & 3) * 2;
#pragma unroll
    for (int i = 0; i < 4; i++) {
        int r0 = rowBase + warpRow + i * 16 + g;
#pragma unroll
        for (int j = 0; j < NJ; j++) {
            int col = warpCol + j * 8 + c2;
            float b0 = s_bias[col], b1 = s_bias[col + 1];
            float2 o0 = make_float2(acc[i][j][0] + b0, acc[i][j][1] + b1);
            float2 o1 = make_float2(acc[i][j][2] + b0, acc[i][j][3] + b1);
            *reinterpret_cast<float2*>(&C[(size_t)r0 * CN + colBase + col]) = o0;
            *reinterpret_cast<float2*>(&C[(size_t)(r0 + 8) * CN + colBase + col]) = o1;
        }
    }
}

// ---------------------------------------------------------------------------
// Flag kernel (validated R13 form; proj row stride now 96)
// ---------------------------------------------------------------------------
#define DELTA 6e-3f
__global__ void flag_kernel(const float* __restrict__ proj,
                            const float* __restrict__ refp,
                            int* __restrict__ list,
                            int* __restrict__ counter) {
    __shared__ int s_cnt, s_base;
    if (threadIdx.x == 0) s_cnt = 0;
    __syncthreads();

    int t = blockIdx.x * 256 + threadIdx.x;  // 16 threads per q, 4 coords each
    int q = t >> 4, part = t & 15;
    float4 o4 = *reinterpret_cast<const float4*>(&proj[(size_t)q * 96 + part * 4]);
    float2 r2 = *reinterpret_cast<const float2*>(&refp[(size_t)q * 2]);
    float o[4] = {o4.x, o4.y, o4.z, o4.w};
    int flags = 0;
#pragma unroll
    for (int j = 0; j < 4; j++) {
        float r = (j & 1) ? r2.y : r2.x;
        float lx = (r + o[j]) * 2.0f - 1.0f;
        float f = (lx + 1.0f) * 64.0f - 0.5f;
        if (fabsf(f - floorf(f) - 0.5f) < DELTA) flags |= 1 << j;
    }
    int cnt = __popc((unsigned)flags);
    int local = 0;
    if (cnt) local = atomicAdd(&s_cnt, cnt);
    __syncthreads();
    if (threadIdx.x == 0 && s_cnt) s_base = atomicAdd(counter, s_cnt);
    __syncthreads();
    if (cnt) {
        int base = s_base + local;
        int idBase = q * 64 + part * 4;
#pragma unroll
        for (int j = 0; j < 4; j++)
            if (flags & (1 << j)) list[base++] = idBase + j;
    }
}

// ---------------------------------------------------------------------------
// Fixup kernel (validated; proj row stride now 96)
// ---------------------------------------------------------------------------
__global__ void fixup_kernel(const int* __restrict__ list,
                             const int* __restrict__ counter,
                             const float* __restrict__ query,
                             const float* __restrict__ Woff,
                             const float* __restrict__ boff,
                             float* __restrict__ proj) {
    int total = counter[0];
    for (int i = blockIdx.x * blockDim.x + threadIdx.x; i < total;
         i += gridDim.x * blockDim.x) {
        int id = list[i];
        int q = id >> 6, col = id & 63;
        const float* qrow = query + (size_t)q * 256;
        const float* wcol = Woff + col;
        float acc = 0.0f;
#pragma unroll
        for (int k0 = 0; k0 < 256; k0 += 8) {
            float qv[8], wv[8];
#pragma unroll
            for (int j = 0; j < 8; j++) qv[j] = qrow[k0 + j];
#pragma unroll
            for (int j = 0; j < 8; j++) wv[j] = wcol[(size_t)(k0 + j) * 64];
#pragma unroll
            for (int j = 0; j < 8; j++) acc += qv[j] * wv[j];
        }
        proj[(size_t)q * 96 + col] = acc + boff[col];
    }
}

// ---------------------------------------------------------------------------
// Sampling kernel — proj stride 96; unconditional gather (ww==0 terms add ±0,
// bitwise-neutral; flat=0 is valid memory) for better load batching/MLP.
// ---------------------------------------------------------------------------
__global__ void sample_kernel(const float* __restrict__ refp,
                              const float* __restrict__ proj,
                              const float* __restrict__ v,
                              float* __restrict__ outw) {
    const int warpsPerBlock = blockDim.x >> 5;
    const int q = blockIdx.x * warpsPerBlock + (threadIdx.x >> 5);
    const int lane = threadIdx.x & 31;
    if (q >= BB * NN) return;
    const int b = q >> 14;

    const float* prow = proj + (size_t)q * 96;
    float logit = prow[64 + lane];
    float m = logit;
    m = fmaxf(m, __shfl_xor_sync(0xffffffffu, m, 1));
    m = fmaxf(m, __shfl_xor_sync(0xffffffffu, m, 2));
    float e = expf(logit - m);
    float s = e;
    s += __shfl_xor_sync(0xffffffffu, s, 1);
    s += __shfl_xor_sync(0xffffffffu, s, 2);
    float w = e / s;

    float rx = refp[(size_t)q * 2 + 0];
    float ry = refp[(size_t)q * 2 + 1];
    float ox = prow[lane * 2 + 0];
    float oy = prow[lane * 2 + 1];
    float lx = (rx + ox) * 2.0f - 1.0f;
    float ly = (ry + oy) * 2.0f - 1.0f;
    float fx = (lx + 1.0f) * 64.0f - 0.5f;
    float fy = (ly + 1.0f) * 64.0f - 0.5f;
    float ixf = rintf(fx);
    float iyf = rintf(fy);
    bool valid = (ixf >= 0.0f) && (ixf < 128.0f) && (iyf >= 0.0f) && (iyf < 128.0f);
    int flat = valid ? ((int)iyf * 128 + (int)ixf) : 0;
    float wv = valid ? w : 0.0f;

    const float* vb = v + (size_t)b * NVV * DD;
    const size_t outBase = (size_t)q * DD;
#pragma unroll
    for (int h = 0; h < NHH; h++) {
        float acc = 0.0f;
#pragma unroll
        for (int p = 0; p < PP; p++) {
            int src = h * 4 + p;
            float ww = __shfl_sync(0xffffffffu, wv, src);
            int fl = __shfl_sync(0xffffffffu, flat, src);
            acc += ww * vb[(size_t)fl * DD + h * 32 + lane];
        }
        outw[outBase + h * 32 + lane] = acc;
    }
}

// ---------------------------------------------------------------------------
extern "C" void kernel_launch(void* const* d_in, const int* in_sizes, int n_in,
                              void* d_out, int out_size) {
    const float* query  = (const float*)d_in[0];
    const float* refp   = (const float*)d_in[1];
    const float* value  = (const float*)d_in[2];
    const float* W_off  = (const float*)d_in[3];
    const float* b_off  = (const float*)d_in[4];
    const float* W_attn = (const float*)d_in[5];
    const float* b_attn = (const float*)d_in[6];
    const float* W_v    = (const float*)d_in[7];
    const float* b_v    = (const float*)d_in[8];
    const float* W_out  = (const float*)d_in[9];
    const float* b_out  = (const float*)d_in[10];
    float* out = (float*)d_out;

    float *gv = nullptr, *gw = nullptr, *gp = nullptr, *gbp = nullptr;
    __nv_bfloat16 *wvh = nullptr, *wvl = nullptr, *woh = nullptr, *wol = nullptr;
    __nv_bfloat16 *wph = nullptr, *wpl = nullptr;
    int *glist = nullptr, *gcnt = nullptr;
    cudaGetSymbolAddress((void**)&gv, g_v);
    cudaGetSymbolAddress((void**)&gw, g_weighted);
    cudaGetSymbolAddress((void**)&gp, g_proj);
    cudaGetSymbolAddress((void**)&gbp, g_bias_p);
    cudaGetSymbolAddress((void**)&wvh, g_wv_hi);
    cudaGetSymbolAddress((void**)&wvl, g_wv_lo);
    cudaGetSymbolAddress((void**)&woh, g_wo_hi);
    cudaGetSymbolAddress((void**)&wol, g_wo_lo);
    cudaGetSymbolAddress((void**)&wph, g_wp_hi);
    cudaGetSymbolAddress((void**)&wpl, g_wp_lo);
    cudaGetSymbolAddress((void**)&glist, g_list);
    cudaGetSymbolAddress((void**)&gcnt, g_count);

    const int M = BB * NN;  // 65536
    const int SMEM = 2 * BUF40 * 2 + 128 * 4;  // 82432
    cudaFuncSetAttribute((const void*)gemm_mma<256, 4>,
                         cudaFuncAttributeMaxDynamicSharedMemorySize, SMEM);
    cudaFuncSetAttribute((const void*)gemm_mma<96, 3>,
                         cudaFuncAttributeMaxDynamicSharedMemorySize, SMEM);

    // 0. prep bf16-split transposed weights (+ counter reset)
    prep_weight<<<256, 256>>>(W_v, wvh, wvl, 256);
    prep_weight<<<256, 256>>>(W_out, woh, wol, 256);
    prep_weight_proj<<<128, 256>>>(W_off, W_attn, b_off, b_attn, wph, wpl,
                                   gbp, gcnt);

    // 1. v = value @ W_v + b_v (128x128 tiles, bf16x3, pipelined — R11)
    gemm_mma<256, 4><<<dim3(2, M / 128), 256, SMEM>>>(value, wvh, wvl, b_v, gv);

    // 2. proj = query @ [W_off|W_attn] — 96 cols, stride 96 (NJ=3)
    gemm_mma<96, 3><<<dim3(1, M / 128), 256, SMEM>>>(query, wph, wpl, gbp, gp);

    // 3. flag band coords, exact fixup
    flag_kernel<<<M * 64 / 1024, 256>>>(gp, refp, glist, gcnt);
    fixup_kernel<<<512, 256>>>(glist, gcnt, query, W_off, b_off, gp);

    // 4. softmax + nearest gather + weighted sum
    sample_kernel<<<M / 8, 256>>>(refp, gp, gv, gw);

    // 5. out = weighted @ W_out + b_out (128x128 tiles, bf16x3, pipelined)
    gemm_mma<256, 4><<<dim3(2, M / 128), 256, SMEM>>>(gw, woh, wol, b_out, out);
}